// round 17
// baseline (speedup 1.0000x reference)
#include <cuda_runtime.h>
#include <cuda_fp16.h>
#include <cstdint>

// Problem shape (fixed for this problem instance)
#define Bb 8
#define Nn 10000
#define Ff 256
#define Hh 128
#define Ee 320000
#define Mm (Bb * Nn)          // 80000 rows
#define SLOT 96               // per-row edge slot capacity (mean deg 32, +11 sigma)

// Scratch (static __device__ arrays; allocation is forbidden)
__device__ __half g_xh[(size_t)Mm * Ff];          // dropout(x) as fp16, 41 MB
__device__ __half g_wh[(size_t)Hh * Ff];          // W transposed [n][k] fp16, 64 KB
__device__ __half g_xw[(size_t)Mm * Hh];          // xw fp16, 20.5 MB
__device__ int    g_cnt[Mm];                      // per-(b,row) edge counts
__device__ int2   g_edge[(size_t)Mm * SLOT];      // slotted {col, val}  61.4 MB

// ---------------------------------------------------------------------------
// helpers
// ---------------------------------------------------------------------------
__device__ __forceinline__ unsigned h2u(__half2 h) { return *(unsigned*)&h; }

__device__ __forceinline__ void mma_f16(float* d, const unsigned* a, const unsigned* b) {
    asm volatile(
        "mma.sync.aligned.m16n8k16.row.col.f32.f16.f16.f32 "
        "{%0,%1,%2,%3}, {%4,%5,%6,%7}, {%8,%9}, {%0,%1,%2,%3};"
        : "+f"(d[0]), "+f"(d[1]), "+f"(d[2]), "+f"(d[3])
        : "r"(a[0]), "r"(a[1]), "r"(a[2]), "r"(a[3]),
          "r"(b[0]), "r"(b[1]));
}

__device__ __forceinline__ void cp16(void* sdst, const void* gsrc) {
    unsigned sa = (unsigned)__cvta_generic_to_shared(sdst);
    asm volatile("cp.async.cg.shared.global [%0], [%1], 16;"
                 :: "r"(sa), "l"(gsrc));
}
#define CP_COMMIT()  asm volatile("cp.async.commit_group;")
#define CP_WAIT(n)   asm volatile("cp.async.wait_group %0;" :: "n"(n))

// ---------------------------------------------------------------------------
// Pre-kernel A: fused inverted dropout + fp16 convert (half of x,u -> g_xh)
// ---------------------------------------------------------------------------
__global__ __launch_bounds__(256) void dropcvt_kernel(
    const float* __restrict__ x, const float* __restrict__ u, size_t base)
{
    size_t i8 = base + (size_t)(blockIdx.x * 256 + threadIdx.x) * 8;
    float4 x0 = *(const float4*)(x + i8);
    float4 x1 = *(const float4*)(x + i8 + 4);
    float4 u0 = *(const float4*)(u + i8);
    float4 u1 = *(const float4*)(u + i8 + 4);
    float a0 = (u0.x > 0.5f) ? 2.0f * x0.x : 0.0f;
    float a1 = (u0.y > 0.5f) ? 2.0f * x0.y : 0.0f;
    float a2 = (u0.z > 0.5f) ? 2.0f * x0.z : 0.0f;
    float a3 = (u0.w > 0.5f) ? 2.0f * x0.w : 0.0f;
    float a4 = (u1.x > 0.5f) ? 2.0f * x1.x : 0.0f;
    float a5 = (u1.y > 0.5f) ? 2.0f * x1.y : 0.0f;
    float a6 = (u1.z > 0.5f) ? 2.0f * x1.z : 0.0f;
    float a7 = (u1.w > 0.5f) ? 2.0f * x1.w : 0.0f;
    uint4 o;
    o.x = h2u(__floats2half2_rn(a0, a1));
    o.y = h2u(__floats2half2_rn(a2, a3));
    o.z = h2u(__floats2half2_rn(a4, a5));
    o.w = h2u(__floats2half2_rn(a6, a7));
    *(uint4*)&g_xh[i8] = o;
}

// ---------------------------------------------------------------------------
// Pre-kernel B: W [k][n] fp32 -> g_wh [n][k] fp16   (tiny: 32768 elements)
// ---------------------------------------------------------------------------
__global__ __launch_bounds__(256) void wcvt_kernel(const float* __restrict__ w)
{
    int i = blockIdx.x * 256 + threadIdx.x;   // i = k*128 + n
    int k = i >> 7, n = i & 127;
    g_wh[n * Ff + k] = __float2half(w[i]);
}

// ---------------------------------------------------------------------------
// GEMM: xw = g_xh @ g_wh^T  (fp16 in, fp32 acc, fp16 out), M-half per launch
// ---------------------------------------------------------------------------
#define STRU 20   // u32 row stride: (20g+t4) mod 32 all-distinct; 80B = 16B-aligned

__global__ __launch_bounds__(256) void gemm_f16_kernel(int rowOff)
{
    __shared__ unsigned sA[3][64][STRU];    // 15,360 B
    __shared__ unsigned sB[3][128][STRU];   // 30,720 B

    const int t    = threadIdx.x;
    const int lane = t & 31;
    const int wid  = t >> 5;
    const int warpM = wid >> 2, warpN = wid & 3;      // 2 x 4 warps
    const int m0w = warpM * 32, n0w = warpN * 32;
    const int g  = lane >> 2, t4 = lane & 3;
    const size_t rowBase = (size_t)rowOff + (size_t)blockIdx.x * 64;

    // cp.async mappings: each chunk-row holds 32 halves = 4 x 16B pieces
    const int arow = t >> 2, ap = t & 3;              // A: 64 rows x 4 pieces
    const __half* aSrc = g_xh + (rowBase + arow) * Ff + ap * 8;

    auto cpChunk = [&](int c, int s) {
        cp16(&sA[s][arow][ap * 4], aSrc + c * 32);
#pragma unroll
        for (int r2 = 0; r2 < 2; r2++) {              // B: 128 rows x 4 pieces
            int idx = t + 256 * r2;
            int brow = idx >> 2, bp = idx & 3;
            cp16(&sB[s][brow][bp * 4], g_wh + brow * Ff + c * 32 + bp * 8);
        }
        CP_COMMIT();
    };

    float acc[2][4][4];
#pragma unroll
    for (int mt = 0; mt < 2; mt++)
#pragma unroll
        for (int nt = 0; nt < 4; nt++)
#pragma unroll
            for (int i = 0; i < 4; i++) acc[mt][nt][i] = 0.0f;

    cpChunk(0, 0);
    cpChunk(1, 1);

#pragma unroll 1
    for (int c = 0; c < Ff / 32; c++) {
        const int pa = c % 3;
        if (c + 2 < Ff / 32) { CP_WAIT(1); } else { CP_WAIT(0); }
        __syncthreads();
        if (c + 2 < Ff / 32) cpChunk(c + 2, (c + 2) % 3);

#pragma unroll
        for (int ks = 0; ks < 2; ks++) {
            const int kc = ks * 8;
            unsigned afr[2][4];
#pragma unroll
            for (int mt = 0; mt < 2; mt++) {
                int m = m0w + mt * 16;
                afr[mt][0] = sA[pa][m + g]    [kc + t4];
                afr[mt][1] = sA[pa][m + g + 8][kc + t4];
                afr[mt][2] = sA[pa][m + g]    [kc + t4 + 4];
                afr[mt][3] = sA[pa][m + g + 8][kc + t4 + 4];
            }
            unsigned bfr[4][2];
#pragma unroll
            for (int nt = 0; nt < 4; nt++) {
                int n = n0w + nt * 8 + g;
                bfr[nt][0] = sB[pa][n][kc + t4];
                bfr[nt][1] = sB[pa][n][kc + t4 + 4];
            }
#pragma unroll
            for (int mt = 0; mt < 2; mt++)
#pragma unroll
                for (int nt = 0; nt < 4; nt++)
                    mma_f16(acc[mt][nt], afr[mt], bfr[nt]);
        }
    }

    // epilogue: fp16 stores
#pragma unroll
    for (int mt = 0; mt < 2; mt++) {
        size_t r0 = rowBase + m0w + mt * 16 + g;
#pragma unroll
        for (int nt = 0; nt < 4; nt++) {
            int c0 = n0w + nt * 8 + 2 * t4;
            *(__half2*)&g_xw[r0 * Hh + c0] =
                __floats2half2_rn(acc[mt][nt][0], acc[mt][nt][1]);
            *(__half2*)&g_xw[(r0 + 8) * Hh + c0] =
                __floats2half2_rn(acc[mt][nt][2], acc[mt][nt][3]);
        }
    }
}

// ---------------------------------------------------------------------------
// Edge build: zero counts, then one slotted-scatter pass.
// ---------------------------------------------------------------------------
__global__ void zero_cnt_kernel()
{
    int i = blockIdx.x * blockDim.x + threadIdx.x;
    if (i < Mm) g_cnt[i] = 0;
}

__global__ __launch_bounds__(256) void build_kernel(
    const int* __restrict__ rows,
    const int* __restrict__ cols,
    const float* __restrict__ vals)
{
    int e = (blockIdx.x * blockDim.x + threadIdx.x) * 4;
    if (e >= Bb * Ee) return;
    int4   r4 = *(const int4*)(rows + e);
    int4   c4 = *(const int4*)(cols + e);
    float4 v4 = *(const float4*)(vals + e);
    int s0 = ((e    ) / Ee) * Nn + r4.x;
    int s1 = ((e + 1) / Ee) * Nn + r4.y;
    int s2 = ((e + 2) / Ee) * Nn + r4.z;
    int s3 = ((e + 3) / Ee) * Nn + r4.w;
    int p0 = atomicAdd(&g_cnt[s0], 1);
    int p1 = atomicAdd(&g_cnt[s1], 1);
    int p2 = atomicAdd(&g_cnt[s2], 1);
    int p3 = atomicAdd(&g_cnt[s3], 1);
    if (p0 < SLOT) g_edge[(size_t)s0 * SLOT + p0] = make_int2(c4.x, __float_as_int(v4.x));
    if (p1 < SLOT) g_edge[(size_t)s1 * SLOT + p1] = make_int2(c4.y, __float_as_int(v4.y));
    if (p2 < SLOT) g_edge[(size_t)s2 * SLOT + p2] = make_int2(c4.z, __float_as_int(v4.z));
    if (p3 < SLOT) g_edge[(size_t)s3 * SLOT + p3] = make_int2(c4.w, __float_as_int(v4.w));
}

// ---------------------------------------------------------------------------
// Gather-accumulate (unchanged; ~64 us, near its L2 floor).
// ---------------------------------------------------------------------------
__device__ __forceinline__ void accum8(float* acc, uint4 s, float v)
{
    float2 f;
    f = __half22float2(*(__half2*)&s.x); acc[0] += v * f.x; acc[1] += v * f.y;
    f = __half22float2(*(__half2*)&s.y); acc[2] += v * f.x; acc[3] += v * f.y;
    f = __half22float2(*(__half2*)&s.z); acc[4] += v * f.x; acc[5] += v * f.y;
    f = __half22float2(*(__half2*)&s.w); acc[6] += v * f.x; acc[7] += v * f.y;
}

__global__ __launch_bounds__(256) void gather_kernel(float4* __restrict__ out)
{
    const int row  = (blockIdx.x * 256 + threadIdx.x) >> 5;  // 0 .. Mm-1
    const int lane = threadIdx.x & 31;
    const int h    = lane >> 4;
    const int l16  = lane & 15;

    int cnt = g_cnt[row];
    if (cnt > SLOT) cnt = SLOT;
    const int2* __restrict__ ep = g_edge + (size_t)row * SLOT;
    const int b = row / Nn;
    const uint4* __restrict__ xwb =
        (const uint4*)g_xw + (size_t)b * Nn * 16;   // 16 uint4 per xw row

    float acc[8] = {0.f, 0.f, 0.f, 0.f, 0.f, 0.f, 0.f, 0.f};

    int i = 0;
    for (; i + 4 <= cnt; i += 4) {
        int2 eA = ep[i + h];
        int2 eB = ep[i + 2 + h];
        uint4 sAq = xwb[(size_t)eA.x * 16 + l16];
        uint4 sBq = xwb[(size_t)eB.x * 16 + l16];
        accum8(acc, sAq, __int_as_float(eA.y));
        accum8(acc, sBq, __int_as_float(eB.y));
    }
    if (i + 2 <= cnt) {
        int2 eA = ep[i + h];
        uint4 sAq = xwb[(size_t)eA.x * 16 + l16];
        accum8(acc, sAq, __int_as_float(eA.y));
        i += 2;
    }
    if (i < cnt && h == 0) {
        int2 e = ep[i];
        uint4 s = xwb[(size_t)e.x * 16 + l16];
        accum8(acc, s, __int_as_float(e.y));
    }

#pragma unroll
    for (int j = 0; j < 8; j++)
        acc[j] += __shfl_xor_sync(0xffffffffu, acc[j], 16);

    float4 o = (h == 0) ? make_float4(acc[0], acc[1], acc[2], acc[3])
                        : make_float4(acc[4], acc[5], acc[6], acc[7]);
    out[(size_t)row * 32 + l16 * 2 + h] = o;
}

// ---------------------------------------------------------------------------
// Launch: 3-stream pipeline.
//   S0 (capture): dropcvtA -> evA -> dropcvtB -> evB -> [evG,evJ] gather
//   S1: zero -> wcvt -> evW -> build -> evJ
//   S2: [evW,evA] gemmA -> [evB] gemmB -> evG
// Both side streams end with a recorded event that S0 waits on (capture rule).
// ---------------------------------------------------------------------------
extern "C" void kernel_launch(void* const* d_in, const int* in_sizes, int n_in,
                              void* d_out, int out_size)
{
    const float* x    = (const float*)d_in[0];
    const float* u    = (const float*)d_in[1];
    const int*   rows = (const int*)d_in[2];
    const int*   cols = (const int*)d_in[3];
    const float* vals = (const float*)d_in[4];
    const float* w    = (const float*)d_in[5];
    float4*      out  = (float4*)d_out;

    static cudaStream_t s1 = nullptr, s2 = nullptr;
    static cudaEvent_t evF = nullptr, evW = nullptr, evJ = nullptr,
                       evA = nullptr, evB = nullptr, evG = nullptr;
    if (s1 == nullptr) {
        cudaStreamCreateWithFlags(&s1, cudaStreamNonBlocking);
        cudaStreamCreateWithFlags(&s2, cudaStreamNonBlocking);
        cudaEventCreateWithFlags(&evF, cudaEventDisableTiming);
        cudaEventCreateWithFlags(&evW, cudaEventDisableTiming);
        cudaEventCreateWithFlags(&evJ, cudaEventDisableTiming);
        cudaEventCreateWithFlags(&evA, cudaEventDisableTiming);
        cudaEventCreateWithFlags(&evB, cudaEventDisableTiming);
        cudaEventCreateWithFlags(&evG, cudaEventDisableTiming);
    }

    const int totalE   = Bb * Ee;                   // 2,560,000
    const int eThreads = totalE / 4;                // 640,000 (4 edges/thread)
    const int halfM    = Mm / 2;                    // 40,000 rows (batches 0-3)
    const int dcBlocks = (halfM * Ff / 8) / 256;    // 5000
    const size_t halfElems = (size_t)halfM * Ff;

    cudaEventRecord(evF, 0);
    cudaStreamWaitEvent(s1, evF, 0);
    cudaStreamWaitEvent(s2, evF, 0);

    // S1: zero counts, W convert, then edge build
    zero_cnt_kernel<<<(Mm + 255) / 256, 256, 0, s1>>>();
    wcvt_kernel<<<(Hh * Ff) / 256, 256, 0, s1>>>(w);
    cudaEventRecord(evW, s1);
    build_kernel<<<eThreads / 256, 256, 0, s1>>>(rows, cols, vals);
    cudaEventRecord(evJ, s1);

    // S0: dropout+cvt, split by M-half
    dropcvt_kernel<<<dcBlocks, 256>>>(x, u, 0);
    cudaEventRecord(evA, 0);
    dropcvt_kernel<<<dcBlocks, 256>>>(x, u, halfElems);
    cudaEventRecord(evB, 0);

    // S2: GEMM halves, overlapped with dropcvtB
    cudaStreamWaitEvent(s2, evW, 0);
    cudaStreamWaitEvent(s2, evA, 0);
    gemm_f16_kernel<<<halfM / 64, 256, 0, s2>>>(0);
    cudaStreamWaitEvent(s2, evB, 0);
    gemm_f16_kernel<<<halfM / 64, 256, 0, s2>>>(halfM);
    cudaEventRecord(evG, s2);

    // S0: gather after GEMM chain and edge build
    cudaStreamWaitEvent(0, evG, 0);
    cudaStreamWaitEvent(0, evJ, 0);
    gather_kernel<<<(Mm * 32) / 256, 256>>>(out);
}